// round 8
// baseline (speedup 1.0000x reference)
#include <cuda_runtime.h>

#define FULLMASK 0xffffffffu
#define B_ 2
#define N_ 8192
#define K_ 16
#define C_ 32
#define GR 16
#define NC (GR * GR * GR)            // 4096 cells per batch
#define NPART 512                    // one partial set per knn warp-block
typedef unsigned long long ull;

static __device__ __forceinline__ float finf() { return __int_as_float(0x7f800000); }

// ---- scratch (device globals; no allocation allowed) ----
__device__ int    g_knn[B_ * N_ * K_];
__device__ float  g_ltv [B_ * N_ * C_];            // varphi
__device__ float2 g_ltpa[B_ * N_ * C_];            // (psi, alpha)
__device__ float  g_part[NPART * 8];
__device__ float  g_stats[8];
// grid structures
__device__ float  g_grid[10];                      // ox,oy,oz,hx,hy,hz,hmin,ihx,ihy,ihz
__device__ int    g_cellcnt[B_ * NC];
__device__ int    g_cellptr[B_ * NC];
__device__ int    g_cellstart[B_ * (NC + 1)];
__device__ int    g_cellid[B_ * N_];
__device__ float4 g_sorted[B_ * N_];               // (-2x,-2y,-2z,|p|^2), cell-grouped
__device__ float4 g_sortedraw[B_ * N_];            // raw xytp, cell-grouped
__device__ int    g_sortidx[B_ * N_];              // original within-batch index

__device__ __forceinline__ float warp_sum(float v) {
#pragma unroll
    for (int off = 16; off; off >>= 1)
        v += __shfl_xor_sync(FULLMASK, v, off);
    return v;
}

// monotone float -> uint32 (total order)
__device__ __forceinline__ unsigned ford(float f) {
    const int b = __float_as_int(f);
    return (unsigned)b ^ (((unsigned)(b >> 31)) | 0x80000000u);
}
__device__ __forceinline__ float funord(unsigned u) {
    const int b = (u & 0x80000000u) ? (int)(u & 0x7fffffffu) : (int)~u;
    return __int_as_float(b);
}

// per-thread sorted top-16 of packed keys (ascending); predicated shift insert
__device__ __forceinline__ void insert_t(ull ck, ull (&k)[16]) {
    bool p[16];
#pragma unroll
    for (int i = 0; i < 16; ++i) p[i] = ck < k[i];
#pragma unroll
    for (int i = 15; i > 0; --i) k[i] = p[i - 1] ? k[i - 1] : (p[i] ? ck : k[i]);
    if (p[0]) k[0] = ck;
}

// scan sorted candidates [s,e): warp-uniform loads, per-thread insert
__device__ __forceinline__ void scan_cells(int s, int e, int boff,
                                           float qx, float qy, float qz,
                                           ull (&k)[16]) {
    for (int i = s; i < e; ++i) {
        const float4 c = g_sorted[boff + i];
        const int idx  = g_sortidx[boff + i];
        const float d  = fmaf(qx, c.x, fmaf(qy, c.y, fmaf(qz, c.z, c.w)));
        const ull ck = ((ull)ford(d) << 13) | (unsigned)idx;
        if (ck < k[15]) insert_t(ck, k);
    }
}

// =====================================================================
// G1: bounds reduce + zero histogram + write grid params (single block)
// =====================================================================
__global__ __launch_bounds__(1024) void grid_setup_kernel(const float4* __restrict__ xytp)
{
    __shared__ float red[6][32];
    for (int i = threadIdx.x; i < B_ * NC; i += 1024) g_cellcnt[i] = 0;

    float mn[3] = { finf(), finf(), finf() };
    float mx[3] = { -finf(), -finf(), -finf() };
    for (int i = threadIdx.x; i < B_ * N_; i += 1024) {
        const float4 v = xytp[i];
        mn[0] = fminf(mn[0], v.x); mx[0] = fmaxf(mx[0], v.x);
        mn[1] = fminf(mn[1], v.y); mx[1] = fmaxf(mx[1], v.y);
        mn[2] = fminf(mn[2], v.z); mx[2] = fmaxf(mx[2], v.z);
    }
#pragma unroll
    for (int off = 16; off; off >>= 1) {
#pragma unroll
        for (int d = 0; d < 3; ++d) {
            mn[d] = fminf(mn[d], __shfl_xor_sync(FULLMASK, mn[d], off));
            mx[d] = fmaxf(mx[d], __shfl_xor_sync(FULLMASK, mx[d], off));
        }
    }
    const int warp = threadIdx.x >> 5, lane = threadIdx.x & 31;
    if (lane == 0) {
#pragma unroll
        for (int d = 0; d < 3; ++d) { red[d][warp] = mn[d]; red[3 + d][warp] = mx[d]; }
    }
    __syncthreads();
    if (threadIdx.x < 32) {
        float a[6];
#pragma unroll
        for (int d = 0; d < 6; ++d) a[d] = red[d][lane];
#pragma unroll
        for (int off = 16; off; off >>= 1) {
#pragma unroll
            for (int d = 0; d < 3; ++d) {
                a[d]     = fminf(a[d],     __shfl_xor_sync(FULLMASK, a[d],     off));
                a[3 + d] = fmaxf(a[3 + d], __shfl_xor_sync(FULLMASK, a[3 + d], off));
            }
        }
        if (lane == 0) {
            float h[3], o[3];
#pragma unroll
            for (int d = 0; d < 3; ++d) {
                o[d] = a[d] - 1e-4f;
                h[d] = fmaxf((a[3 + d] - a[d] + 2e-4f) * (1.f / GR), 1e-6f);
            }
            g_grid[0] = o[0]; g_grid[1] = o[1]; g_grid[2] = o[2];
            g_grid[3] = h[0]; g_grid[4] = h[1]; g_grid[5] = h[2];
            g_grid[6] = fminf(h[0], fminf(h[1], h[2]));
            g_grid[7] = 1.f / h[0]; g_grid[8] = 1.f / h[1]; g_grid[9] = 1.f / h[2];
        }
    }
}

// =====================================================================
// G2: per-point cell id + histogram
// =====================================================================
__global__ __launch_bounds__(256) void cell_hist_kernel(const float4* __restrict__ xytp)
{
    const int i = blockIdx.x * 256 + threadIdx.x;
    const int b = i >> 13;
    const float4 v = xytp[i];
    const int cx = min(GR - 1, max(0, (int)((v.x - g_grid[0]) * g_grid[7])));
    const int cy = min(GR - 1, max(0, (int)((v.y - g_grid[1]) * g_grid[8])));
    const int cz = min(GR - 1, max(0, (int)((v.z - g_grid[2]) * g_grid[9])));
    const int cid = (cz * GR + cy) * GR + cx;
    g_cellid[i] = cid;
    atomicAdd(&g_cellcnt[b * NC + cid], 1);
}

// =====================================================================
// G3: exclusive prefix scan of 4096 counts per batch (block per batch)
// =====================================================================
__global__ __launch_bounds__(1024) void prefix_kernel()
{
    __shared__ int wsum[32];
    const int b = blockIdx.x, t = threadIdx.x;
    const int lane = t & 31, warp = t >> 5;
    const int base = b * NC + t * 4;
    const int v0 = g_cellcnt[base + 0];
    const int v1 = g_cellcnt[base + 1];
    const int v2 = g_cellcnt[base + 2];
    const int v3 = g_cellcnt[base + 3];
    const int ts = v0 + v1 + v2 + v3;
    int sc = ts;
#pragma unroll
    for (int off = 1; off < 32; off <<= 1) {
        const int n = __shfl_up_sync(FULLMASK, sc, off);
        if (lane >= off) sc += n;
    }
    if (lane == 31) wsum[warp] = sc;
    __syncthreads();
    if (warp == 0) {
        int ws = wsum[lane];
#pragma unroll
        for (int off = 1; off < 32; off <<= 1) {
            const int n = __shfl_up_sync(FULLMASK, ws, off);
            if (lane >= off) ws += n;
        }
        wsum[lane] = ws;
    }
    __syncthreads();
    const int excl = sc - ts + (warp ? wsum[warp - 1] : 0);
    const int o = b * (NC + 1) + t * 4;
    const int e1 = excl + v0, e2 = e1 + v1, e3 = e2 + v2;
    g_cellstart[o + 0] = excl; g_cellstart[o + 1] = e1;
    g_cellstart[o + 2] = e2;   g_cellstart[o + 3] = e3;
    g_cellptr[base + 0] = excl; g_cellptr[base + 1] = e1;
    g_cellptr[base + 2] = e2;   g_cellptr[base + 3] = e3;
    if (t == 1023) g_cellstart[b * (NC + 1) + NC] = e3 + v3;
}

// =====================================================================
// G4: scatter points into cell-grouped order (transformed + raw)
// =====================================================================
__global__ __launch_bounds__(256) void scatter_kernel(const float4* __restrict__ xytp)
{
    const int i = blockIdx.x * 256 + threadIdx.x;
    const int b = i >> 13;
    const int cid = g_cellid[i];
    const int pos = atomicAdd(&g_cellptr[b * NC + cid], 1);
    const float4 v = xytp[i];
    const float n2 = fmaf(v.z, v.z, fmaf(v.y, v.y, v.x * v.x));
    g_sorted   [b * N_ + pos] = make_float4(-2.f * v.x, -2.f * v.y, -2.f * v.z, n2);
    g_sortedraw[b * N_ + pos] = v;
    g_sortidx  [b * N_ + pos] = i & (N_ - 1);
}

// =====================================================================
// KNN: THREAD per query (cell-sorted), warp-union shell scan,
//      per-thread register top-16, fused PE-stats partials.
//      One warp per block (32-thread blocks, 512 blocks).
// =====================================================================
__global__ __launch_bounds__(32) void knn_kernel(const float4* __restrict__ xytp,
                                                 const float* __restrict__ pe_w1,
                                                 const float* __restrict__ pe_b1)
{
    const int lane = threadIdx.x;
    const int sp   = blockIdx.x * 32 + lane;       // GLOBAL sorted position
    const int b    = sp >> 13;
    const int boff = b * N_;
    const int csb  = b * (NC + 1);

    const float4 q = g_sortedraw[sp];              // FIXED: sp already global
    const int    p = g_sortidx[sp] + boff;         // FIXED: original flat index
    const float qn2 = fmaf(q.z, q.z, fmaf(q.y, q.y, q.x * q.x));
    const float hmin = g_grid[6];

    int cx = min(GR - 1, max(0, (int)((q.x - g_grid[0]) * g_grid[7])));
    int cy = min(GR - 1, max(0, (int)((q.y - g_grid[1]) * g_grid[8])));
    int cz = min(GR - 1, max(0, (int)((q.z - g_grid[2]) * g_grid[9])));

    // warp union box
    int x0 = cx, x1 = cx, y0 = cy, y1 = cy, z0 = cz, z1 = cz;
#pragma unroll
    for (int off = 16; off; off >>= 1) {
        x0 = min(x0, __shfl_xor_sync(FULLMASK, x0, off));
        x1 = max(x1, __shfl_xor_sync(FULLMASK, x1, off));
        y0 = min(y0, __shfl_xor_sync(FULLMASK, y0, off));
        y1 = max(y1, __shfl_xor_sync(FULLMASK, y1, off));
        z0 = min(z0, __shfl_xor_sync(FULLMASK, z0, off));
        z1 = max(z1, __shfl_xor_sync(FULLMASK, z1, off));
    }
    const int rcap = max(max(max(x0, GR - 1 - x1), max(y0, GR - 1 - y1)),
                         max(z0, GR - 1 - z1));

    ull k[16];
#pragma unroll
    for (int i = 0; i < 16; ++i) k[i] = ~0ULL;

    for (int r = 0;; ++r) {
        if (r > 0) {
            const float d16t = funord((unsigned)(k[15] >> 13)) + qn2;
            const float rim  = (float)(r - 1) * hmin;
            const bool done  = (rim * rim >= fmaf(d16t, 1.0001f, 1e-5f));
            if (__all_sync(FULLMASK, done)) break;
            if (r > rcap) break;
        }
        if (r == 0) {
            for (int z = z0; z <= z1; ++z)
                for (int y = y0; y <= y1; ++y) {
                    const int row = csb + (z * GR + y) * GR;
                    scan_cells(g_cellstart[row + x0], g_cellstart[row + x1 + 1],
                               boff, q.x, q.y, q.z, k);
                }
        } else {
            for (int z = z0 - r; z <= z1 + r; ++z) {
                if ((unsigned)z >= (unsigned)GR) continue;
                const bool zedge = (z == z0 - r) || (z == z1 + r);
                for (int y = y0 - r; y <= y1 + r; ++y) {
                    if ((unsigned)y >= (unsigned)GR) continue;
                    const bool yedge = (y == y0 - r) || (y == y1 + r);
                    const int row = csb + (z * GR + y) * GR;
                    if (zedge || yedge) {
                        const int xa = max(x0 - r, 0), xb = min(x1 + r, GR - 1);
                        scan_cells(g_cellstart[row + xa], g_cellstart[row + xb + 1],
                                   boff, q.x, q.y, q.z, k);
                    } else {
                        const int xl = x0 - r, xr = x1 + r;
                        if (xl >= 0)
                            scan_cells(g_cellstart[row + xl], g_cellstart[row + xl + 1],
                                       boff, q.x, q.y, q.z, k);
                        if (xr < GR)
                            scan_cells(g_cellstart[row + xr], g_cellstart[row + xr + 1],
                                       boff, q.x, q.y, q.z, k);
                    }
                }
            }
        }
    }

    // write neighbor list (ascending (d, idx) == reference top_k order)
    int ids[16];
#pragma unroll
    for (int i = 0; i < 16; ++i) {
        ids[i] = (int)(k[i] & 8191ULL);
        g_knn[(size_t)p * K_ + i] = ids[i];
    }

    // ---- fused PE-stats partials over this thread's 16 neighbors ----
    float w1[16], b1v[4];
#pragma unroll
    for (int i = 0; i < 16; ++i) w1[i] = pe_w1[i];
#pragma unroll
    for (int f = 0; f < 4; ++f) b1v[f] = pe_b1[f];

    float acc[8];
#pragma unroll
    for (int i = 0; i < 8; ++i) acc[i] = 0.f;
#pragma unroll
    for (int kk = 0; kk < 16; ++kk) {
        const float4 nb = xytp[boff + ids[kk]];
        const float r0 = q.x - nb.x, r1 = q.y - nb.y, r2 = q.z - nb.z, r3 = q.w - nb.w;
#pragma unroll
        for (int f = 0; f < 4; ++f) {
            float h = b1v[f];
            h = fmaf(r0, w1[f * 4 + 0], h);
            h = fmaf(r1, w1[f * 4 + 1], h);
            h = fmaf(r2, w1[f * 4 + 2], h);
            h = fmaf(r3, w1[f * 4 + 3], h);
            acc[f]     += h;
            acc[4 + f]  = fmaf(h, h, acc[4 + f]);
        }
    }
#pragma unroll
    for (int i = 0; i < 8; ++i) acc[i] = warp_sum(acc[i]);
    if (lane < 8)
        g_part[(size_t)blockIdx.x * 8 + lane] = acc[lane];
}

// =====================================================================
// lt: per-point linear transform; split layout (varphi | (psi,alpha))
// =====================================================================
__global__ __launch_bounds__(256) void lt_kernel(const float* __restrict__ features,
                                                 const float* __restrict__ lt_w,
                                                 const float* __restrict__ lt_b)
{
    __shared__ float w[96 * 32];
    __shared__ float bias[96];
    for (int i = threadIdx.x; i < 96 * 32; i += 256) w[i] = lt_w[i];
    if (threadIdx.x < 96) bias[threadIdx.x] = lt_b[threadIdx.x];
    __syncthreads();

    const int p = blockIdx.x * 256 + threadIdx.x;
    float4 f4[8];
    const float4* fr = (const float4*)(features + (size_t)p * C_);
#pragma unroll
    for (int i = 0; i < 8; ++i) f4[i] = fr[i];

#pragma unroll 2
    for (int ch = 0; ch < 32; ++ch) {
        float av = bias[ch], as = bias[32 + ch], aa = bias[64 + ch];
        const float4* wv = (const float4*)(w + ch * 32);
        const float4* ws = (const float4*)(w + (32 + ch) * 32);
        const float4* wa = (const float4*)(w + (64 + ch) * 32);
#pragma unroll
        for (int i = 0; i < 8; ++i) {
            const float4 a = wv[i], s = ws[i], c = wa[i], f = f4[i];
            av = fmaf(f.x, a.x, av); av = fmaf(f.y, a.y, av);
            av = fmaf(f.z, a.z, av); av = fmaf(f.w, a.w, av);
            as = fmaf(f.x, s.x, as); as = fmaf(f.y, s.y, as);
            as = fmaf(f.z, s.z, as); as = fmaf(f.w, s.w, as);
            aa = fmaf(f.x, c.x, aa); aa = fmaf(f.y, c.y, aa);
            aa = fmaf(f.z, c.z, aa); aa = fmaf(f.w, c.w, aa);
        }
        g_ltv [(size_t)p * 32 + ch] = av;
        g_ltpa[(size_t)p * 32 + ch] = make_float2(as, aa);
    }
}

// =====================================================================
// finalize stats (parallel, fixed-order => deterministic)
// =====================================================================
__global__ __launch_bounds__(256) void pe_finalize_kernel()
{
    __shared__ float red[32 * 8];
    __shared__ float tot8[8];
    const int t = threadIdx.x;
    const int ch = t & 7, grp = t >> 3;
    float s = 0.f;
    const int base = grp * (NPART / 32);
    for (int i = 0; i < NPART / 32; ++i) s += g_part[(base + i) * 8 + ch];
    red[grp * 8 + ch] = s;
    __syncthreads();
    if (t < 8) {
        float tt = 0.f;
        for (int g = 0; g < 32; ++g) tt += red[g * 8 + t];
        tot8[t] = tt;
    }
    __syncthreads();
    if (t < 4) {
        const float invc = 1.f / (float)(B_ * N_ * K_);
        const float mean = tot8[t] * invc;
        const float var  = fmaf(tot8[4 + t], invc, -mean * mean);
        g_stats[t]     = mean;
        g_stats[4 + t] = rsqrtf(var + 1e-5f);
    }
}

// =====================================================================
// fused main — warp per point, lane = channel
// =====================================================================
__global__ __launch_bounds__(256) void main_kernel(const float4* __restrict__ xytp,
                                                   const float* __restrict__ pe_w1,
                                                   const float* __restrict__ pe_b1,
                                                   const float* __restrict__ pe_gamma,
                                                   const float* __restrict__ pe_beta,
                                                   const float* __restrict__ pe_w2,
                                                   const float* __restrict__ pe_b2,
                                                   const float* __restrict__ ln_gamma,
                                                   const float* __restrict__ ln_beta,
                                                   float* __restrict__ out)
{
    const int warp = threadIdx.x >> 5;
    const int lane = threadIdx.x & 31;
    const int p    = blockIdx.x * 8 + warp;
    const int b    = p >> 13;

    float w1[16], b1v[4], mean[4], rstd[4], gam[4], bet[4], w2a[4];
#pragma unroll
    for (int i = 0; i < 16; ++i) w1[i] = pe_w1[i];
#pragma unroll
    for (int f = 0; f < 4; ++f) {
        b1v[f]  = pe_b1[f];
        mean[f] = g_stats[f];
        rstd[f] = g_stats[4 + f];
        gam[f]  = pe_gamma[f];
        bet[f]  = pe_beta[f];
    }
    {
        const float4 w2 = ((const float4*)pe_w2)[lane];
        w2a[0] = w2.x; w2a[1] = w2.y; w2a[2] = w2.z; w2a[3] = w2.w;
    }
    const float b2 = pe_b2[lane];
    const float lg = ln_gamma[lane];
    const float lb = ln_beta[lane];

    const float  varphi = g_ltv[(size_t)p * 32 + lane];
    const float4 q      = xytp[p];
    const int    myidx  = g_knn[(size_t)p * K_ + (lane & 15)];

    float lgt[16], av[16];
#pragma unroll
    for (int k = 0; k < 16; ++k) {
        const int j = __shfl_sync(FULLMASK, myidx, k);
        const float4 nb = xytp[(size_t)b * N_ + j];
        const float r0 = q.x - nb.x, r1 = q.y - nb.y, r2 = q.z - nb.z, r3 = q.w - nb.w;

        float del = b2;
#pragma unroll
        for (int f = 0; f < 4; ++f) {
            float h = b1v[f];
            h = fmaf(r0, w1[f * 4 + 0], h);
            h = fmaf(r1, w1[f * 4 + 1], h);
            h = fmaf(r2, w1[f * 4 + 2], h);
            h = fmaf(r3, w1[f * 4 + 3], h);
            float u = (h - mean[f]) * rstd[f];
            u = fmaf(u, gam[f], bet[f]);
            u = fmaxf(u, 0.f);
            del = fmaf(u, w2a[f], del);
        }

        const float2 pa = g_ltpa[((size_t)b * N_ + j) * 32 + lane];

        const float pre = (varphi - pa.x) + del;
        const float s1  = warp_sum(pre);
        const float s2  = warp_sum(pre * pre);
        const float mu  = s1 * (1.f / 32.f);
        const float var = fmaf(s2, 1.f / 32.f, -mu * mu);
        const float rs  = rsqrtf(var + 1e-5f);
        lgt[k] = fmaf((pre - mu) * rs, lg, lb);
        av[k]  = pa.y + del;
    }

    float m = -finf();
#pragma unroll
    for (int k = 0; k < 16; ++k) m = fmaxf(m, lgt[k]);
    const float inv_scale = 0.17677669529663687f;   // 1/sqrt(32)
    float se = 0.f, acc = 0.f;
#pragma unroll
    for (int k = 0; k < 16; ++k) {
        const float e = __expf((lgt[k] - m) * inv_scale);
        se  += e;
        acc  = fmaf(e, av[k], acc);
    }
    out[(size_t)p * C_ + lane] = acc / se;
}

// =====================================================================
// Launch
// =====================================================================
extern "C" void kernel_launch(void* const* d_in, const int* in_sizes, int n_in,
                              void* d_out, int out_size)
{
    const float* xytp     = (const float*)d_in[0];
    const float* features = (const float*)d_in[1];
    const float* pe_w1    = (const float*)d_in[2];
    const float* pe_b1    = (const float*)d_in[3];
    const float* pe_gamma = (const float*)d_in[4];
    const float* pe_beta  = (const float*)d_in[5];
    const float* pe_w2    = (const float*)d_in[6];
    const float* pe_b2    = (const float*)d_in[7];
    const float* lt_w     = (const float*)d_in[8];
    const float* lt_b     = (const float*)d_in[9];
    const float* ln_gamma = (const float*)d_in[10];
    const float* ln_beta  = (const float*)d_in[11];
    float* out = (float*)d_out;
    const float4* xp4 = (const float4*)xytp;

    grid_setup_kernel<<<1, 1024>>>(xp4);
    cell_hist_kernel<<<(B_ * N_) / 256, 256>>>(xp4);
    prefix_kernel<<<B_, 1024>>>();
    scatter_kernel<<<(B_ * N_) / 256, 256>>>(xp4);
    knn_kernel<<<(B_ * N_) / 32, 32>>>(xp4, pe_w1, pe_b1);
    lt_kernel<<<(B_ * N_) / 256, 256>>>(features, lt_w, lt_b);
    pe_finalize_kernel<<<1, 256>>>();
    main_kernel<<<(B_ * N_) / 8, 256>>>(xp4, pe_w1, pe_b1,
                                        pe_gamma, pe_beta, pe_w2, pe_b2,
                                        ln_gamma, ln_beta, out);
}

// round 9
// speedup vs baseline: 3.6771x; 3.6771x over previous
#include <cuda_runtime.h>

#define FULLMASK 0xffffffffu
#define B_ 2
#define N_ 8192
#define K_ 16
#define C_ 32
#define GR 16
#define NC (GR * GR * GR)            // 4096 cells per batch
#define WPB 8                        // warps (queries) per knn block
#define KNN_BLOCKS ((B_ * N_) / WPB) // 2048
#define NPART KNN_BLOCKS
typedef unsigned long long ull;

static __device__ __forceinline__ float finf() { return __int_as_float(0x7f800000); }

// ---- scratch (device globals; no allocation allowed) ----
__device__ int    g_knn[B_ * N_ * K_];
__device__ float  g_ltv [B_ * N_ * C_];            // varphi
__device__ float2 g_ltpa[B_ * N_ * C_];            // (psi, alpha)
__device__ float  g_part[NPART * 8];
__device__ float  g_stats[8];
// grid structures
__device__ float  g_grid[10];                      // ox,oy,oz,hx,hy,hz,hmin,ihx,ihy,ihz
__device__ int    g_cellcnt[B_ * NC];
__device__ int    g_cellptr[B_ * NC];
__device__ int    g_cellstart[B_ * (NC + 1)];
__device__ int    g_cellid[B_ * N_];
__device__ float4 g_sorted[B_ * N_];               // (-2x,-2y,-2z,|p|^2), cell-grouped
__device__ float4 g_sortedraw[B_ * N_];            // raw xytp, cell-grouped
__device__ int    g_sortidx[B_ * N_];              // original within-batch index

__device__ __forceinline__ float warp_sum(float v) {
#pragma unroll
    for (int off = 16; off; off >>= 1)
        v += __shfl_xor_sync(FULLMASK, v, off);
    return v;
}

// monotone float -> uint32 (total order)
__device__ __forceinline__ unsigned ford(float f) {
    const int b = __float_as_int(f);
    return (unsigned)b ^ (((unsigned)(b >> 31)) | 0x80000000u);
}
__device__ __forceinline__ float funord(unsigned u) {
    const int b = (u & 0x80000000u) ? (int)(u & 0x7fffffffu) : (int)~u;
    return __int_as_float(b);
}

// warp-wide min of 64-bit keys via two 32-bit reduce_min
__device__ __forceinline__ ull warp_min_ull(ull v) {
    const unsigned hi = (unsigned)(v >> 32);
    const unsigned lo = (unsigned)v;
    const unsigned mh = __reduce_min_sync(FULLMASK, hi);
    const unsigned lo2 = (hi == mh) ? lo : 0xFFFFFFFFu;
    const unsigned ml = __reduce_min_sync(FULLMASK, lo2);
    return ((ull)mh << 32) | ml;
}

// per-lane sorted top-16 (ascending); predicated shift insert
__device__ __forceinline__ void insert_t(ull ck, ull (&k)[16]) {
    bool p[16];
#pragma unroll
    for (int i = 0; i < 16; ++i) p[i] = ck < k[i];
#pragma unroll
    for (int i = 15; i > 0; --i) k[i] = p[i - 1] ? k[i - 1] : (p[i] ? ck : k[i]);
    if (p[0]) k[0] = ck;
}

// lane-strided scan of sorted candidates [s,e): each lane keeps its own top-16
__device__ __forceinline__ void scan_row(int s, int e, int boff, int lane,
                                         float qx, float qy, float qz,
                                         ull (&k)[16]) {
    for (int i = s + lane; i < e; i += 32) {
        const float4 c = g_sorted[boff + i];
        const int idx  = g_sortidx[boff + i];
        const float d  = fmaf(qx, c.x, fmaf(qy, c.y, fmaf(qz, c.z, c.w)));
        const ull ck = ((ull)ford(d) << 13) | (unsigned)idx;
        if (ck < k[15]) insert_t(ck, k);
    }
}

// =====================================================================
// G1: bounds reduce + zero histogram + write grid params (single block)
// =====================================================================
__global__ __launch_bounds__(1024) void grid_setup_kernel(const float4* __restrict__ xytp)
{
    __shared__ float red[6][32];
    for (int i = threadIdx.x; i < B_ * NC; i += 1024) g_cellcnt[i] = 0;

    float mn[3] = { finf(), finf(), finf() };
    float mx[3] = { -finf(), -finf(), -finf() };
    for (int i = threadIdx.x; i < B_ * N_; i += 1024) {
        const float4 v = xytp[i];
        mn[0] = fminf(mn[0], v.x); mx[0] = fmaxf(mx[0], v.x);
        mn[1] = fminf(mn[1], v.y); mx[1] = fmaxf(mx[1], v.y);
        mn[2] = fminf(mn[2], v.z); mx[2] = fmaxf(mx[2], v.z);
    }
#pragma unroll
    for (int off = 16; off; off >>= 1) {
#pragma unroll
        for (int d = 0; d < 3; ++d) {
            mn[d] = fminf(mn[d], __shfl_xor_sync(FULLMASK, mn[d], off));
            mx[d] = fmaxf(mx[d], __shfl_xor_sync(FULLMASK, mx[d], off));
        }
    }
    const int warp = threadIdx.x >> 5, lane = threadIdx.x & 31;
    if (lane == 0) {
#pragma unroll
        for (int d = 0; d < 3; ++d) { red[d][warp] = mn[d]; red[3 + d][warp] = mx[d]; }
    }
    __syncthreads();
    if (threadIdx.x < 32) {
        float a[6];
#pragma unroll
        for (int d = 0; d < 6; ++d) a[d] = red[d][lane];
#pragma unroll
        for (int off = 16; off; off >>= 1) {
#pragma unroll
            for (int d = 0; d < 3; ++d) {
                a[d]     = fminf(a[d],     __shfl_xor_sync(FULLMASK, a[d],     off));
                a[3 + d] = fmaxf(a[3 + d], __shfl_xor_sync(FULLMASK, a[3 + d], off));
            }
        }
        if (lane == 0) {
            float h[3], o[3];
#pragma unroll
            for (int d = 0; d < 3; ++d) {
                o[d] = a[d] - 1e-4f;
                h[d] = fmaxf((a[3 + d] - a[d] + 2e-4f) * (1.f / GR), 1e-6f);
            }
            g_grid[0] = o[0]; g_grid[1] = o[1]; g_grid[2] = o[2];
            g_grid[3] = h[0]; g_grid[4] = h[1]; g_grid[5] = h[2];
            g_grid[6] = fminf(h[0], fminf(h[1], h[2]));
            g_grid[7] = 1.f / h[0]; g_grid[8] = 1.f / h[1]; g_grid[9] = 1.f / h[2];
        }
    }
}

// =====================================================================
// G2: per-point cell id + histogram
// =====================================================================
__global__ __launch_bounds__(256) void cell_hist_kernel(const float4* __restrict__ xytp)
{
    const int i = blockIdx.x * 256 + threadIdx.x;
    const int b = i >> 13;
    const float4 v = xytp[i];
    const int cx = min(GR - 1, max(0, (int)((v.x - g_grid[0]) * g_grid[7])));
    const int cy = min(GR - 1, max(0, (int)((v.y - g_grid[1]) * g_grid[8])));
    const int cz = min(GR - 1, max(0, (int)((v.z - g_grid[2]) * g_grid[9])));
    const int cid = (cz * GR + cy) * GR + cx;
    g_cellid[i] = cid;
    atomicAdd(&g_cellcnt[b * NC + cid], 1);
}

// =====================================================================
// G3: exclusive prefix scan of 4096 counts per batch (block per batch)
// =====================================================================
__global__ __launch_bounds__(1024) void prefix_kernel()
{
    __shared__ int wsum[32];
    const int b = blockIdx.x, t = threadIdx.x;
    const int lane = t & 31, warp = t >> 5;
    const int base = b * NC + t * 4;
    const int v0 = g_cellcnt[base + 0];
    const int v1 = g_cellcnt[base + 1];
    const int v2 = g_cellcnt[base + 2];
    const int v3 = g_cellcnt[base + 3];
    const int ts = v0 + v1 + v2 + v3;
    int sc = ts;
#pragma unroll
    for (int off = 1; off < 32; off <<= 1) {
        const int n = __shfl_up_sync(FULLMASK, sc, off);
        if (lane >= off) sc += n;
    }
    if (lane == 31) wsum[warp] = sc;
    __syncthreads();
    if (warp == 0) {
        int ws = wsum[lane];
#pragma unroll
        for (int off = 1; off < 32; off <<= 1) {
            const int n = __shfl_up_sync(FULLMASK, ws, off);
            if (lane >= off) ws += n;
        }
        wsum[lane] = ws;
    }
    __syncthreads();
    const int excl = sc - ts + (warp ? wsum[warp - 1] : 0);
    const int o = b * (NC + 1) + t * 4;
    const int e1 = excl + v0, e2 = e1 + v1, e3 = e2 + v2;
    g_cellstart[o + 0] = excl; g_cellstart[o + 1] = e1;
    g_cellstart[o + 2] = e2;   g_cellstart[o + 3] = e3;
    g_cellptr[base + 0] = excl; g_cellptr[base + 1] = e1;
    g_cellptr[base + 2] = e2;   g_cellptr[base + 3] = e3;
    if (t == 1023) g_cellstart[b * (NC + 1) + NC] = e3 + v3;
}

// =====================================================================
// G4: scatter points into cell-grouped order (transformed + raw)
// =====================================================================
__global__ __launch_bounds__(256) void scatter_kernel(const float4* __restrict__ xytp)
{
    const int i = blockIdx.x * 256 + threadIdx.x;
    const int b = i >> 13;
    const int cid = g_cellid[i];
    const int pos = atomicAdd(&g_cellptr[b * NC + cid], 1);
    const float4 v = xytp[i];
    const float n2 = fmaf(v.z, v.z, fmaf(v.y, v.y, v.x * v.x));
    g_sorted   [b * N_ + pos] = make_float4(-2.f * v.x, -2.f * v.y, -2.f * v.z, n2);
    g_sortedraw[b * N_ + pos] = v;
    g_sortidx  [b * N_ + pos] = i & (N_ - 1);
}

// =====================================================================
// KNN: WARP per query (cell-sorted order), lane-local top-16 + one merge,
//      expanding shells with cheap sound bound; fused PE-stats partials.
// =====================================================================
__global__ __launch_bounds__(32 * WPB) void knn_kernel(const float4* __restrict__ xytp,
                                                       const float* __restrict__ pe_w1,
                                                       const float* __restrict__ pe_b1)
{
    __shared__ float sred[WPB * 8];
    const int tid  = threadIdx.x;
    const int warp = tid >> 5;
    const int lane = tid & 31;
    const int sp   = blockIdx.x * WPB + warp;      // global sorted position
    const int b    = sp >> 13;
    const int boff = b * N_;
    const int csb  = b * (NC + 1);

    const float4 q  = g_sortedraw[sp];
    const int porig = g_sortidx[sp] + boff;        // original flat point index
    const float qn2 = fmaf(q.z, q.z, fmaf(q.y, q.y, q.x * q.x));
    const float hmin = g_grid[6];

    const int cx = min(GR - 1, max(0, (int)((q.x - g_grid[0]) * g_grid[7])));
    const int cy = min(GR - 1, max(0, (int)((q.y - g_grid[1]) * g_grid[8])));
    const int cz = min(GR - 1, max(0, (int)((q.z - g_grid[2]) * g_grid[9])));
    const int rcap = max(max(cx, GR - 1 - cx),
                     max(max(cy, GR - 1 - cy), max(cz, GR - 1 - cz)));

    ull loc[16];
#pragma unroll
    for (int i = 0; i < 16; ++i) loc[i] = ~0ULL;

    // ---- initial box: r <= 1 (rows along x) ----
    {
        const int za = max(cz - 1, 0), zb = min(cz + 1, GR - 1);
        const int ya = max(cy - 1, 0), yb = min(cy + 1, GR - 1);
        const int xa = max(cx - 1, 0), xb = min(cx + 1, GR - 1);
        for (int z = za; z <= zb; ++z)
            for (int y = ya; y <= yb; ++y) {
                const int row = csb + (z * GR + y) * GR;
                scan_row(g_cellstart[row + xa], g_cellstart[row + xb + 1],
                         boff, lane, q.x, q.y, q.z, loc);
            }
    }

    // ---- expanding shells r >= 2 ----
    for (int r = 2; r <= rcap; ++r) {
        // sound bound: the lane achieving min(k15) holds 16 keys <= it
        const ull bnd = warp_min_ull(loc[15]);
        const float d16 = funord((unsigned)(bnd >> 13)) + qn2;
        const float rim = (float)(r - 1) * hmin;
        if (rim * rim >= fmaf(d16, 1.0001f, 1e-5f)) break;

        for (int z = cz - r; z <= cz + r; ++z) {
            if ((unsigned)z >= (unsigned)GR) continue;
            const bool zedge = (z == cz - r) || (z == cz + r);
            for (int y = cy - r; y <= cy + r; ++y) {
                if ((unsigned)y >= (unsigned)GR) continue;
                const bool yedge = (y == cy - r) || (y == cy + r);
                const int row = csb + (z * GR + y) * GR;
                if (zedge || yedge) {
                    const int xa = max(cx - r, 0), xb = min(cx + r, GR - 1);
                    scan_row(g_cellstart[row + xa], g_cellstart[row + xb + 1],
                             boff, lane, q.x, q.y, q.z, loc);
                } else {
                    const int xl = cx - r, xr = cx + r;
                    if (xl >= 0)
                        scan_row(g_cellstart[row + xl], g_cellstart[row + xl + 1],
                                 boff, lane, q.x, q.y, q.z, loc);
                    if (xr < GR)
                        scan_row(g_cellstart[row + xr], g_cellstart[row + xr + 1],
                                 boff, lane, q.x, q.y, q.z, loc);
                }
            }
        }
    }

    // ---- merge: 16 extract-min rounds (keys globally unique) ----
    ull mykey = ~0ULL;
#pragma unroll
    for (int rd = 0; rd < 16; ++rd) {
        const ull mk = warp_min_ull(loc[0]);
        if (loc[0] == mk) {          // unique winner lane
#pragma unroll
            for (int i = 0; i < 15; ++i) loc[i] = loc[i + 1];
            loc[15] = ~0ULL;
        }
        if (lane == rd) mykey = mk;
    }
    const int myidx = (int)(mykey & 8191ULL);
    if (lane < 16)
        g_knn[(size_t)porig * K_ + lane] = myidx;   // ascending (d, idx) = top_k order

    // ---- fused PE-stats partials (lanes 0..15 hold the 16 neighbors) ----
    float acc[8];
#pragma unroll
    for (int i = 0; i < 8; ++i) acc[i] = 0.f;
    if (lane < 16) {
        const float4 nb = xytp[boff + myidx];
        const float r0 = q.x - nb.x, r1 = q.y - nb.y, r2 = q.z - nb.z, r3 = q.w - nb.w;
#pragma unroll
        for (int f = 0; f < 4; ++f) {
            float h = pe_b1[f];
            h = fmaf(r0, pe_w1[f * 4 + 0], h);
            h = fmaf(r1, pe_w1[f * 4 + 1], h);
            h = fmaf(r2, pe_w1[f * 4 + 2], h);
            h = fmaf(r3, pe_w1[f * 4 + 3], h);
            acc[f]     = h;
            acc[4 + f] = h * h;
        }
    }
#pragma unroll
    for (int i = 0; i < 8; ++i) acc[i] = warp_sum(acc[i]);
    if (lane == 0) {
#pragma unroll
        for (int i = 0; i < 8; ++i) sred[warp * 8 + i] = acc[i];
    }
    __syncthreads();
    if (tid < 8) {
        float s = 0.f;
#pragma unroll
        for (int w = 0; w < WPB; ++w) s += sred[w * 8 + tid];
        g_part[(size_t)blockIdx.x * 8 + tid] = s;
    }
}

// =====================================================================
// lt: per-point linear transform; split layout (varphi | (psi,alpha))
// =====================================================================
__global__ __launch_bounds__(256) void lt_kernel(const float* __restrict__ features,
                                                 const float* __restrict__ lt_w,
                                                 const float* __restrict__ lt_b)
{
    __shared__ float w[96 * 32];
    __shared__ float bias[96];
    for (int i = threadIdx.x; i < 96 * 32; i += 256) w[i] = lt_w[i];
    if (threadIdx.x < 96) bias[threadIdx.x] = lt_b[threadIdx.x];
    __syncthreads();

    const int p = blockIdx.x * 256 + threadIdx.x;
    float4 f4[8];
    const float4* fr = (const float4*)(features + (size_t)p * C_);
#pragma unroll
    for (int i = 0; i < 8; ++i) f4[i] = fr[i];

#pragma unroll 2
    for (int ch = 0; ch < 32; ++ch) {
        float av = bias[ch], as = bias[32 + ch], aa = bias[64 + ch];
        const float4* wv = (const float4*)(w + ch * 32);
        const float4* ws = (const float4*)(w + (32 + ch) * 32);
        const float4* wa = (const float4*)(w + (64 + ch) * 32);
#pragma unroll
        for (int i = 0; i < 8; ++i) {
            const float4 a = wv[i], s = ws[i], c = wa[i], f = f4[i];
            av = fmaf(f.x, a.x, av); av = fmaf(f.y, a.y, av);
            av = fmaf(f.z, a.z, av); av = fmaf(f.w, a.w, av);
            as = fmaf(f.x, s.x, as); as = fmaf(f.y, s.y, as);
            as = fmaf(f.z, s.z, as); as = fmaf(f.w, s.w, as);
            aa = fmaf(f.x, c.x, aa); aa = fmaf(f.y, c.y, aa);
            aa = fmaf(f.z, c.z, aa); aa = fmaf(f.w, c.w, aa);
        }
        g_ltv [(size_t)p * 32 + ch] = av;
        g_ltpa[(size_t)p * 32 + ch] = make_float2(as, aa);
    }
}

// =====================================================================
// finalize stats (parallel, fixed-order => deterministic)
// =====================================================================
__global__ __launch_bounds__(256) void pe_finalize_kernel()
{
    __shared__ float red[32 * 8];
    __shared__ float tot8[8];
    const int t = threadIdx.x;
    const int ch = t & 7, grp = t >> 3;       // 32 groups of (NPART/32) partials
    float s = 0.f;
    const int base = grp * (NPART / 32);
    for (int i = 0; i < NPART / 32; ++i) s += g_part[(base + i) * 8 + ch];
    red[grp * 8 + ch] = s;
    __syncthreads();
    if (t < 8) {
        float tt = 0.f;
        for (int g = 0; g < 32; ++g) tt += red[g * 8 + t];
        tot8[t] = tt;
    }
    __syncthreads();
    if (t < 4) {
        const float invc = 1.f / (float)(B_ * N_ * K_);
        const float mean = tot8[t] * invc;
        const float var  = fmaf(tot8[4 + t], invc, -mean * mean);
        g_stats[t]     = mean;
        g_stats[4 + t] = rsqrtf(var + 1e-5f);
    }
}

// =====================================================================
// fused main — warp per point, lane = channel
// =====================================================================
__global__ __launch_bounds__(256) void main_kernel(const float4* __restrict__ xytp,
                                                   const float* __restrict__ pe_w1,
                                                   const float* __restrict__ pe_b1,
                                                   const float* __restrict__ pe_gamma,
                                                   const float* __restrict__ pe_beta,
                                                   const float* __restrict__ pe_w2,
                                                   const float* __restrict__ pe_b2,
                                                   const float* __restrict__ ln_gamma,
                                                   const float* __restrict__ ln_beta,
                                                   float* __restrict__ out)
{
    const int warp = threadIdx.x >> 5;
    const int lane = threadIdx.x & 31;
    const int p    = blockIdx.x * 8 + warp;
    const int b    = p >> 13;

    float w1[16], b1v[4], mean[4], rstd[4], gam[4], bet[4], w2a[4];
#pragma unroll
    for (int i = 0; i < 16; ++i) w1[i] = pe_w1[i];
#pragma unroll
    for (int f = 0; f < 4; ++f) {
        b1v[f]  = pe_b1[f];
        mean[f] = g_stats[f];
        rstd[f] = g_stats[4 + f];
        gam[f]  = pe_gamma[f];
        bet[f]  = pe_beta[f];
    }
    {
        const float4 w2 = ((const float4*)pe_w2)[lane];
        w2a[0] = w2.x; w2a[1] = w2.y; w2a[2] = w2.z; w2a[3] = w2.w;
    }
    const float b2 = pe_b2[lane];
    const float lg = ln_gamma[lane];
    const float lb = ln_beta[lane];

    const float  varphi = g_ltv[(size_t)p * 32 + lane];
    const float4 q      = xytp[p];
    const int    myidx  = g_knn[(size_t)p * K_ + (lane & 15)];

    float lgt[16], av[16];
#pragma unroll
    for (int k = 0; k < 16; ++k) {
        const int j = __shfl_sync(FULLMASK, myidx, k);
        const float4 nb = xytp[(size_t)b * N_ + j];
        const float r0 = q.x - nb.x, r1 = q.y - nb.y, r2 = q.z - nb.z, r3 = q.w - nb.w;

        float del = b2;
#pragma unroll
        for (int f = 0; f < 4; ++f) {
            float h = b1v[f];
            h = fmaf(r0, w1[f * 4 + 0], h);
            h = fmaf(r1, w1[f * 4 + 1], h);
            h = fmaf(r2, w1[f * 4 + 2], h);
            h = fmaf(r3, w1[f * 4 + 3], h);
            float u = (h - mean[f]) * rstd[f];
            u = fmaf(u, gam[f], bet[f]);
            u = fmaxf(u, 0.f);
            del = fmaf(u, w2a[f], del);
        }

        const float2 pa = g_ltpa[((size_t)b * N_ + j) * 32 + lane];

        const float pre = (varphi - pa.x) + del;
        const float s1  = warp_sum(pre);
        const float s2  = warp_sum(pre * pre);
        const float mu  = s1 * (1.f / 32.f);
        const float var = fmaf(s2, 1.f / 32.f, -mu * mu);
        const float rs  = rsqrtf(var + 1e-5f);
        lgt[k] = fmaf((pre - mu) * rs, lg, lb);
        av[k]  = pa.y + del;
    }

    float m = -finf();
#pragma unroll
    for (int k = 0; k < 16; ++k) m = fmaxf(m, lgt[k]);
    const float inv_scale = 0.17677669529663687f;   // 1/sqrt(32)
    float se = 0.f, acc = 0.f;
#pragma unroll
    for (int k = 0; k < 16; ++k) {
        const float e = __expf((lgt[k] - m) * inv_scale);
        se  += e;
        acc  = fmaf(e, av[k], acc);
    }
    out[(size_t)p * C_ + lane] = acc / se;
}

// =====================================================================
// Launch
// =====================================================================
extern "C" void kernel_launch(void* const* d_in, const int* in_sizes, int n_in,
                              void* d_out, int out_size)
{
    const float* xytp     = (const float*)d_in[0];
    const float* features = (const float*)d_in[1];
    const float* pe_w1    = (const float*)d_in[2];
    const float* pe_b1    = (const float*)d_in[3];
    const float* pe_gamma = (const float*)d_in[4];
    const float* pe_beta  = (const float*)d_in[5];
    const float* pe_w2    = (const float*)d_in[6];
    const float* pe_b2    = (const float*)d_in[7];
    const float* lt_w     = (const float*)d_in[8];
    const float* lt_b     = (const float*)d_in[9];
    const float* ln_gamma = (const float*)d_in[10];
    const float* ln_beta  = (const float*)d_in[11];
    float* out = (float*)d_out;
    const float4* xp4 = (const float4*)xytp;

    grid_setup_kernel<<<1, 1024>>>(xp4);
    cell_hist_kernel<<<(B_ * N_) / 256, 256>>>(xp4);
    prefix_kernel<<<B_, 1024>>>();
    scatter_kernel<<<(B_ * N_) / 256, 256>>>(xp4);
    knn_kernel<<<KNN_BLOCKS, 32 * WPB>>>(xp4, pe_w1, pe_b1);
    lt_kernel<<<(B_ * N_) / 256, 256>>>(features, lt_w, lt_b);
    pe_finalize_kernel<<<1, 256>>>();
    main_kernel<<<(B_ * N_) / 8, 256>>>(xp4, pe_w1, pe_b1,
                                        pe_gamma, pe_beta, pe_w2, pe_b2,
                                        ln_gamma, ln_beta, out);
}

// round 10
// speedup vs baseline: 7.0012x; 1.9040x over previous
#include <cuda_runtime.h>

#define FULLMASK 0xffffffffu
#define B_ 2
#define N_ 8192
#define K_ 16
#define C_ 32
#define GR 16
#define NC (GR * GR * GR)            // 4096 cells per batch
#define WPB 16                       // warps (queries) per knn block
#define KNN_BLOCKS ((B_ * N_) / WPB) // 1024
#define NPART KNN_BLOCKS

static __device__ __forceinline__ float finf() { return __int_as_float(0x7f800000); }

// ---- scratch (device globals; no allocation allowed) ----
__device__ int    g_knn[B_ * N_ * K_];
__device__ float  g_ltv [B_ * N_ * C_];            // varphi
__device__ float2 g_ltpa[B_ * N_ * C_];            // (psi, alpha)
__device__ float  g_part[NPART * 8];
__device__ float  g_stats[8];
// grid structures
__device__ float  g_grid[10];                      // ox,oy,oz,hx,hy,hz,hmin,ihx,ihy,ihz
__device__ int    g_cellcnt[B_ * NC];
__device__ int    g_cellptr[B_ * NC];
__device__ int    g_cellstart[B_ * (NC + 1)];
__device__ int    g_cellid[B_ * N_];
__device__ float4 g_sorted[B_ * N_];               // (-2x,-2y,-2z,|p|^2), cell-grouped
__device__ float4 g_sortedraw[B_ * N_];            // raw xytp, cell-grouped
__device__ int    g_sortidx[B_ * N_];              // original within-batch index

__device__ __forceinline__ float warp_sum(float v) {
#pragma unroll
    for (int off = 16; off; off >>= 1)
        v += __shfl_xor_sync(FULLMASK, v, off);
    return v;
}

// lexicographic (d, idx) stable insert into sorted list in lanes 0..15
__device__ __forceinline__ void insert_lex(float dv, int iv, int lane,
                                           float& ld, int& li, float& cmax)
{
    const unsigned m = __ballot_sync(FULLMASK,
                         (ld < dv) || (ld == dv && li < iv));
    const int pos = __popc(m & 0xFFFFu);
    const float pld = __shfl_up_sync(FULLMASK, ld, 1);
    const int   pli = __shfl_up_sync(FULLMASK, li, 1);
    if (lane < 16) {
        if (lane > pos)       { ld = pld; li = pli; }
        else if (lane == pos) { ld = dv;  li = iv;  }
    }
    cmax = __shfl_sync(FULLMASK, ld, 15);
}

// scan sorted candidates [s, e) against one query; maintain warp top-16
__device__ __forceinline__ void scan_range(int s, int e, int boff, float4 qp, int lane,
                                           float& ld, int& li, float& cmax)
{
    for (int s0 = s; s0 < e; s0 += 32) {
        const int ii = s0 + lane;
        float d = finf();
        int idx = 0;
        bool v = false;
        if (ii < e) {
            const float4 c = g_sorted[boff + ii];
            idx = g_sortidx[boff + ii];
            d = fmaf(qp.x, c.x, fmaf(qp.y, c.y, fmaf(qp.z, c.z, c.w)));
            v = (d <= cmax);
        }
        unsigned bal = __ballot_sync(FULLMASK, v);
        while (bal) {
            const int src = __ffs(bal) - 1; bal &= bal - 1;
            const float dv = __shfl_sync(FULLMASK, d,   src);
            const int   iv = __shfl_sync(FULLMASK, idx, src);
            if (dv <= cmax) insert_lex(dv, iv, lane, ld, li, cmax);
        }
    }
}

// =====================================================================
// G1: bounds reduce + zero histogram + write grid params (single block)
// =====================================================================
__global__ __launch_bounds__(1024) void grid_setup_kernel(const float4* __restrict__ xytp)
{
    __shared__ float red[6][32];
    for (int i = threadIdx.x; i < B_ * NC; i += 1024) g_cellcnt[i] = 0;

    float mn[3] = { finf(), finf(), finf() };
    float mx[3] = { -finf(), -finf(), -finf() };
    for (int i = threadIdx.x; i < B_ * N_; i += 1024) {
        const float4 v = xytp[i];
        mn[0] = fminf(mn[0], v.x); mx[0] = fmaxf(mx[0], v.x);
        mn[1] = fminf(mn[1], v.y); mx[1] = fmaxf(mx[1], v.y);
        mn[2] = fminf(mn[2], v.z); mx[2] = fmaxf(mx[2], v.z);
    }
#pragma unroll
    for (int off = 16; off; off >>= 1) {
#pragma unroll
        for (int d = 0; d < 3; ++d) {
            mn[d] = fminf(mn[d], __shfl_xor_sync(FULLMASK, mn[d], off));
            mx[d] = fmaxf(mx[d], __shfl_xor_sync(FULLMASK, mx[d], off));
        }
    }
    const int warp = threadIdx.x >> 5, lane = threadIdx.x & 31;
    if (lane == 0) {
#pragma unroll
        for (int d = 0; d < 3; ++d) { red[d][warp] = mn[d]; red[3 + d][warp] = mx[d]; }
    }
    __syncthreads();
    if (threadIdx.x < 32) {
        float a[6];
#pragma unroll
        for (int d = 0; d < 6; ++d) a[d] = red[d][lane];
#pragma unroll
        for (int off = 16; off; off >>= 1) {
#pragma unroll
            for (int d = 0; d < 3; ++d) {
                a[d]     = fminf(a[d],     __shfl_xor_sync(FULLMASK, a[d],     off));
                a[3 + d] = fmaxf(a[3 + d], __shfl_xor_sync(FULLMASK, a[3 + d], off));
            }
        }
        if (lane == 0) {
            float h[3], o[3];
#pragma unroll
            for (int d = 0; d < 3; ++d) {
                o[d] = a[d] - 1e-4f;
                h[d] = fmaxf((a[3 + d] - a[d] + 2e-4f) * (1.f / GR), 1e-6f);
            }
            g_grid[0] = o[0]; g_grid[1] = o[1]; g_grid[2] = o[2];
            g_grid[3] = h[0]; g_grid[4] = h[1]; g_grid[5] = h[2];
            g_grid[6] = fminf(h[0], fminf(h[1], h[2]));
            g_grid[7] = 1.f / h[0]; g_grid[8] = 1.f / h[1]; g_grid[9] = 1.f / h[2];
        }
    }
}

// =====================================================================
// G2: per-point cell id + histogram
// =====================================================================
__global__ __launch_bounds__(256) void cell_hist_kernel(const float4* __restrict__ xytp)
{
    const int i = blockIdx.x * 256 + threadIdx.x;
    const int b = i >> 13;
    const float4 v = xytp[i];
    const int cx = min(GR - 1, max(0, (int)((v.x - g_grid[0]) * g_grid[7])));
    const int cy = min(GR - 1, max(0, (int)((v.y - g_grid[1]) * g_grid[8])));
    const int cz = min(GR - 1, max(0, (int)((v.z - g_grid[2]) * g_grid[9])));
    const int cid = (cz * GR + cy) * GR + cx;
    g_cellid[i] = cid;
    atomicAdd(&g_cellcnt[b * NC + cid], 1);
}

// =====================================================================
// G3: exclusive prefix scan of 4096 counts per batch (block per batch)
// =====================================================================
__global__ __launch_bounds__(1024) void prefix_kernel()
{
    __shared__ int wsum[32];
    const int b = blockIdx.x, t = threadIdx.x;
    const int lane = t & 31, warp = t >> 5;
    const int base = b * NC + t * 4;
    const int v0 = g_cellcnt[base + 0];
    const int v1 = g_cellcnt[base + 1];
    const int v2 = g_cellcnt[base + 2];
    const int v3 = g_cellcnt[base + 3];
    const int ts = v0 + v1 + v2 + v3;
    int sc = ts;
#pragma unroll
    for (int off = 1; off < 32; off <<= 1) {
        const int n = __shfl_up_sync(FULLMASK, sc, off);
        if (lane >= off) sc += n;
    }
    if (lane == 31) wsum[warp] = sc;
    __syncthreads();
    if (warp == 0) {
        int ws = wsum[lane];
#pragma unroll
        for (int off = 1; off < 32; off <<= 1) {
            const int n = __shfl_up_sync(FULLMASK, ws, off);
            if (lane >= off) ws += n;
        }
        wsum[lane] = ws;
    }
    __syncthreads();
    const int excl = sc - ts + (warp ? wsum[warp - 1] : 0);
    const int o = b * (NC + 1) + t * 4;
    const int e1 = excl + v0, e2 = e1 + v1, e3 = e2 + v2;
    g_cellstart[o + 0] = excl; g_cellstart[o + 1] = e1;
    g_cellstart[o + 2] = e2;   g_cellstart[o + 3] = e3;
    g_cellptr[base + 0] = excl; g_cellptr[base + 1] = e1;
    g_cellptr[base + 2] = e2;   g_cellptr[base + 3] = e3;
    if (t == 1023) g_cellstart[b * (NC + 1) + NC] = e3 + v3;
}

// =====================================================================
// G4: scatter points into cell-grouped order (transformed + raw)
// =====================================================================
__global__ __launch_bounds__(256) void scatter_kernel(const float4* __restrict__ xytp)
{
    const int i = blockIdx.x * 256 + threadIdx.x;
    const int b = i >> 13;
    const int cid = g_cellid[i];
    const int pos = atomicAdd(&g_cellptr[b * NC + cid], 1);
    const float4 v = xytp[i];
    const float n2 = fmaf(v.z, v.z, fmaf(v.y, v.y, v.x * v.x));
    g_sorted   [b * N_ + pos] = make_float4(-2.f * v.x, -2.f * v.y, -2.f * v.z, n2);
    g_sortedraw[b * N_ + pos] = v;
    g_sortidx  [b * N_ + pos] = i & (N_ - 1);
}

// =====================================================================
// KNN: warp per query in CELL-SORTED order, ballot-scan + collective
//      sorted insert (R6 machinery), merged r<=1 box, shells from r=2.
//      16 warps/block for latency hiding. Fused PE-stats partials.
// =====================================================================
__global__ __launch_bounds__(32 * WPB) void knn_kernel(const float4* __restrict__ xytp,
                                                       const float* __restrict__ pe_w1,
                                                       const float* __restrict__ pe_b1)
{
    __shared__ float sred[WPB * 8];
    const int tid  = threadIdx.x;
    const int warp = tid >> 5;
    const int lane = tid & 31;
    const int sp   = blockIdx.x * WPB + warp;      // global sorted position
    const int b    = sp >> 13;
    const int boff = b * N_;
    const int csb  = b * (NC + 1);

    const float4 q  = g_sortedraw[sp];
    const int porig = g_sortidx[sp] + boff;        // original flat point index
    const float qn2 = fmaf(q.z, q.z, fmaf(q.y, q.y, q.x * q.x));
    const float hmin = g_grid[6];

    const int cx = min(GR - 1, max(0, (int)((q.x - g_grid[0]) * g_grid[7])));
    const int cy = min(GR - 1, max(0, (int)((q.y - g_grid[1]) * g_grid[8])));
    const int cz = min(GR - 1, max(0, (int)((q.z - g_grid[2]) * g_grid[9])));
    const int rcap = max(max(cx, GR - 1 - cx),
                     max(max(cy, GR - 1 - cy), max(cz, GR - 1 - cz)));

    float ld = finf(); int li = 0; float cmax = finf();

    // ---- merged box r <= 1 (full x-rows) ----
    {
        const int za = max(cz - 1, 0), zb = min(cz + 1, GR - 1);
        const int ya = max(cy - 1, 0), yb = min(cy + 1, GR - 1);
        const int xa = max(cx - 1, 0), xb = min(cx + 1, GR - 1);
        for (int z = za; z <= zb; ++z)
            for (int y = ya; y <= yb; ++y) {
                const int row = csb + (z * GR + y) * GR;
                scan_range(g_cellstart[row + xa], g_cellstart[row + xb + 1],
                           boff, q, lane, ld, li, cmax);
            }
    }

    // ---- expanding shells r >= 2 ----
    for (int r = 2; r <= rcap; ++r) {
        const float rim = (float)(r - 1) * hmin;
        if (rim * rim >= fmaf(cmax + qn2, 1.0001f, 1e-5f)) break;

        for (int z = cz - r; z <= cz + r; ++z) {
            if ((unsigned)z >= (unsigned)GR) continue;
            const bool zedge = (z == cz - r) || (z == cz + r);
            for (int y = cy - r; y <= cy + r; ++y) {
                if ((unsigned)y >= (unsigned)GR) continue;
                const bool yedge = (y == cy - r) || (y == cy + r);
                const int row = csb + (z * GR + y) * GR;
                if (zedge || yedge) {
                    const int xa = max(cx - r, 0), xb = min(cx + r, GR - 1);
                    scan_range(g_cellstart[row + xa], g_cellstart[row + xb + 1],
                               boff, q, lane, ld, li, cmax);
                } else {
                    const int xl = cx - r, xr = cx + r;
                    if (xl >= 0)
                        scan_range(g_cellstart[row + xl], g_cellstart[row + xl + 1],
                                   boff, q, lane, ld, li, cmax);
                    if (xr < GR)
                        scan_range(g_cellstart[row + xr], g_cellstart[row + xr + 1],
                                   boff, q, lane, ld, li, cmax);
                }
            }
        }
    }

    if (lane < 16)
        g_knn[(size_t)porig * K_ + lane] = li;     // ascending (d, idx) = top_k order

    // ---- fused PE-stats partials (lanes 0..15 hold the 16 neighbors) ----
    float acc[8];
#pragma unroll
    for (int i = 0; i < 8; ++i) acc[i] = 0.f;
    if (lane < 16) {
        const float4 nb = xytp[boff + li];
        const float r0 = q.x - nb.x, r1 = q.y - nb.y, r2 = q.z - nb.z, r3 = q.w - nb.w;
#pragma unroll
        for (int f = 0; f < 4; ++f) {
            float h = pe_b1[f];
            h = fmaf(r0, pe_w1[f * 4 + 0], h);
            h = fmaf(r1, pe_w1[f * 4 + 1], h);
            h = fmaf(r2, pe_w1[f * 4 + 2], h);
            h = fmaf(r3, pe_w1[f * 4 + 3], h);
            acc[f]     = h;
            acc[4 + f] = h * h;
        }
    }
#pragma unroll
    for (int i = 0; i < 8; ++i) acc[i] = warp_sum(acc[i]);
    if (lane == 0) {
#pragma unroll
        for (int i = 0; i < 8; ++i) sred[warp * 8 + i] = acc[i];
    }
    __syncthreads();
    if (tid < 8) {
        float s = 0.f;
#pragma unroll
        for (int w = 0; w < WPB; ++w) s += sred[w * 8 + tid];
        g_part[(size_t)blockIdx.x * 8 + tid] = s;
    }
}

// =====================================================================
// lt: per-point linear transform; split layout (varphi | (psi,alpha))
// =====================================================================
__global__ __launch_bounds__(256) void lt_kernel(const float* __restrict__ features,
                                                 const float* __restrict__ lt_w,
                                                 const float* __restrict__ lt_b)
{
    __shared__ float w[96 * 32];
    __shared__ float bias[96];
    for (int i = threadIdx.x; i < 96 * 32; i += 256) w[i] = lt_w[i];
    if (threadIdx.x < 96) bias[threadIdx.x] = lt_b[threadIdx.x];
    __syncthreads();

    const int p = blockIdx.x * 256 + threadIdx.x;
    float4 f4[8];
    const float4* fr = (const float4*)(features + (size_t)p * C_);
#pragma unroll
    for (int i = 0; i < 8; ++i) f4[i] = fr[i];

#pragma unroll 2
    for (int ch = 0; ch < 32; ++ch) {
        float av = bias[ch], as = bias[32 + ch], aa = bias[64 + ch];
        const float4* wv = (const float4*)(w + ch * 32);
        const float4* ws = (const float4*)(w + (32 + ch) * 32);
        const float4* wa = (const float4*)(w + (64 + ch) * 32);
#pragma unroll
        for (int i = 0; i < 8; ++i) {
            const float4 a = wv[i], s = ws[i], c = wa[i], f = f4[i];
            av = fmaf(f.x, a.x, av); av = fmaf(f.y, a.y, av);
            av = fmaf(f.z, a.z, av); av = fmaf(f.w, a.w, av);
            as = fmaf(f.x, s.x, as); as = fmaf(f.y, s.y, as);
            as = fmaf(f.z, s.z, as); as = fmaf(f.w, s.w, as);
            aa = fmaf(f.x, c.x, aa); aa = fmaf(f.y, c.y, aa);
            aa = fmaf(f.z, c.z, aa); aa = fmaf(f.w, c.w, aa);
        }
        g_ltv [(size_t)p * 32 + ch] = av;
        g_ltpa[(size_t)p * 32 + ch] = make_float2(as, aa);
    }
}

// =====================================================================
// finalize stats (parallel, fixed-order => deterministic)
// =====================================================================
__global__ __launch_bounds__(256) void pe_finalize_kernel()
{
    __shared__ float red[32 * 8];
    __shared__ float tot8[8];
    const int t = threadIdx.x;
    const int ch = t & 7, grp = t >> 3;       // 32 groups of (NPART/32) partials
    float s = 0.f;
    const int base = grp * (NPART / 32);
    for (int i = 0; i < NPART / 32; ++i) s += g_part[(base + i) * 8 + ch];
    red[grp * 8 + ch] = s;
    __syncthreads();
    if (t < 8) {
        float tt = 0.f;
        for (int g = 0; g < 32; ++g) tt += red[g * 8 + t];
        tot8[t] = tt;
    }
    __syncthreads();
    if (t < 4) {
        const float invc = 1.f / (float)(B_ * N_ * K_);
        const float mean = tot8[t] * invc;
        const float var  = fmaf(tot8[4 + t], invc, -mean * mean);
        g_stats[t]     = mean;
        g_stats[4 + t] = rsqrtf(var + 1e-5f);
    }
}

// =====================================================================
// fused main — warp per point, lane = channel
// =====================================================================
__global__ __launch_bounds__(256) void main_kernel(const float4* __restrict__ xytp,
                                                   const float* __restrict__ pe_w1,
                                                   const float* __restrict__ pe_b1,
                                                   const float* __restrict__ pe_gamma,
                                                   const float* __restrict__ pe_beta,
                                                   const float* __restrict__ pe_w2,
                                                   const float* __restrict__ pe_b2,
                                                   const float* __restrict__ ln_gamma,
                                                   const float* __restrict__ ln_beta,
                                                   float* __restrict__ out)
{
    const int warp = threadIdx.x >> 5;
    const int lane = threadIdx.x & 31;
    const int p    = blockIdx.x * 8 + warp;
    const int b    = p >> 13;

    float w1[16], b1v[4], mean[4], rstd[4], gam[4], bet[4], w2a[4];
#pragma unroll
    for (int i = 0; i < 16; ++i) w1[i] = pe_w1[i];
#pragma unroll
    for (int f = 0; f < 4; ++f) {
        b1v[f]  = pe_b1[f];
        mean[f] = g_stats[f];
        rstd[f] = g_stats[4 + f];
        gam[f]  = pe_gamma[f];
        bet[f]  = pe_beta[f];
    }
    {
        const float4 w2 = ((const float4*)pe_w2)[lane];
        w2a[0] = w2.x; w2a[1] = w2.y; w2a[2] = w2.z; w2a[3] = w2.w;
    }
    const float b2 = pe_b2[lane];
    const float lg = ln_gamma[lane];
    const float lb = ln_beta[lane];

    const float  varphi = g_ltv[(size_t)p * 32 + lane];
    const float4 q      = xytp[p];
    const int    myidx  = g_knn[(size_t)p * K_ + (lane & 15)];

    float lgt[16], av[16];
#pragma unroll
    for (int k = 0; k < 16; ++k) {
        const int j = __shfl_sync(FULLMASK, myidx, k);
        const float4 nb = xytp[(size_t)b * N_ + j];
        const float r0 = q.x - nb.x, r1 = q.y - nb.y, r2 = q.z - nb.z, r3 = q.w - nb.w;

        float del = b2;
#pragma unroll
        for (int f = 0; f < 4; ++f) {
            float h = b1v[f];
            h = fmaf(r0, w1[f * 4 + 0], h);
            h = fmaf(r1, w1[f * 4 + 1], h);
            h = fmaf(r2, w1[f * 4 + 2], h);
            h = fmaf(r3, w1[f * 4 + 3], h);
            float u = (h - mean[f]) * rstd[f];
            u = fmaf(u, gam[f], bet[f]);
            u = fmaxf(u, 0.f);
            del = fmaf(u, w2a[f], del);
        }

        const float2 pa = g_ltpa[((size_t)b * N_ + j) * 32 + lane];

        const float pre = (varphi - pa.x) + del;
        const float s1  = warp_sum(pre);
        const float s2  = warp_sum(pre * pre);
        const float mu  = s1 * (1.f / 32.f);
        const float var = fmaf(s2, 1.f / 32.f, -mu * mu);
        const float rs  = rsqrtf(var + 1e-5f);
        lgt[k] = fmaf((pre - mu) * rs, lg, lb);
        av[k]  = pa.y + del;
    }

    float m = -finf();
#pragma unroll
    for (int k = 0; k < 16; ++k) m = fmaxf(m, lgt[k]);
    const float inv_scale = 0.17677669529663687f;   // 1/sqrt(32)
    float se = 0.f, acc = 0.f;
#pragma unroll
    for (int k = 0; k < 16; ++k) {
        const float e = __expf((lgt[k] - m) * inv_scale);
        se  += e;
        acc  = fmaf(e, av[k], acc);
    }
    out[(size_t)p * C_ + lane] = acc / se;
}

// =====================================================================
// Launch
// =====================================================================
extern "C" void kernel_launch(void* const* d_in, const int* in_sizes, int n_in,
                              void* d_out, int out_size)
{
    const float* xytp     = (const float*)d_in[0];
    const float* features = (const float*)d_in[1];
    const float* pe_w1    = (const float*)d_in[2];
    const float* pe_b1    = (const float*)d_in[3];
    const float* pe_gamma = (const float*)d_in[4];
    const float* pe_beta  = (const float*)d_in[5];
    const float* pe_w2    = (const float*)d_in[6];
    const float* pe_b2    = (const float*)d_in[7];
    const float* lt_w     = (const float*)d_in[8];
    const float* lt_b     = (const float*)d_in[9];
    const float* ln_gamma = (const float*)d_in[10];
    const float* ln_beta  = (const float*)d_in[11];
    float* out = (float*)d_out;
    const float4* xp4 = (const float4*)xytp;

    grid_setup_kernel<<<1, 1024>>>(xp4);
    cell_hist_kernel<<<(B_ * N_) / 256, 256>>>(xp4);
    prefix_kernel<<<B_, 1024>>>();
    scatter_kernel<<<(B_ * N_) / 256, 256>>>(xp4);
    knn_kernel<<<KNN_BLOCKS, 32 * WPB>>>(xp4, pe_w1, pe_b1);
    lt_kernel<<<(B_ * N_) / 256, 256>>>(features, lt_w, lt_b);
    pe_finalize_kernel<<<1, 256>>>();
    main_kernel<<<(B_ * N_) / 8, 256>>>(xp4, pe_w1, pe_b1,
                                        pe_gamma, pe_beta, pe_w2, pe_b2,
                                        ln_gamma, ln_beta, out);
}

// round 11
// speedup vs baseline: 8.1046x; 1.1576x over previous
#include <cuda_runtime.h>

#define FULLMASK 0xffffffffu
#define B_ 2
#define N_ 8192
#define K_ 16
#define C_ 32
#define GR 16
#define NC (GR * GR * GR)            // 4096 cells per batch
#define KNN_WPB 8                    // warps per knn block
#define KNN_BLOCKS ((B_ * N_) / KNN_WPB)   // 2048
#define NPART KNN_BLOCKS

static __device__ __forceinline__ float finf() { return __int_as_float(0x7f800000); }

// ---- scratch (device globals; no allocation allowed) ----
__device__ int    g_knn[B_ * N_ * K_];
__device__ float  g_ltv [B_ * N_ * C_];            // varphi
__device__ float2 g_ltpa[B_ * N_ * C_];            // (psi, alpha)
__device__ float  g_part[NPART * 8];
__device__ float  g_stats[8];
// grid structures
__device__ float  g_grid[10];                      // ox,oy,oz,hx,hy,hz,hmin,ihx,ihy,ihz
__device__ int    g_cellcnt[B_ * NC];
__device__ int    g_cellptr[B_ * NC];
__device__ int    g_cellstart[B_ * (NC + 1)];
__device__ int    g_cellid[B_ * N_];
__device__ float4 g_sorted[B_ * N_];               // (-2x,-2y,-2z,|p|^2), cell-grouped
__device__ int    g_sortidx[B_ * N_];              // original within-batch index

__device__ __forceinline__ float warp_sum(float v) {
#pragma unroll
    for (int off = 16; off; off >>= 1)
        v += __shfl_xor_sync(FULLMASK, v, off);
    return v;
}

// lexicographic (d, idx) insert into sorted list in lanes 0..15.
// Inserting an element worse than the 16th is a no-op (pos == 16).
__device__ __forceinline__ void insert_lex(float dv, int iv, int lane,
                                           float& ld, int& li)
{
    const unsigned m = __ballot_sync(FULLMASK,
                         (ld < dv) || (ld == dv && li < iv));
    const int pos = __popc(m & 0xFFFFu);
    const float pld = __shfl_up_sync(FULLMASK, ld, 1);
    const int   pli = __shfl_up_sync(FULLMASK, li, 1);
    if (lane < 16) {
        if (lane > pos)       { ld = pld; li = pli; }
        else if (lane == pos) { ld = dv;  li = iv;  }
    }
}

// scan sorted candidates [s, e) against one query; maintain warp top-16.
// Deferred cmax: threshold refreshed once per ballot group, not per insert.
__device__ __forceinline__ void scan_range(int s, int e, int boff, float4 qp, int lane,
                                           float& ld, int& li, float& cmax)
{
    for (int s0 = s; s0 < e; s0 += 32) {
        const int ii = s0 + lane;
        float d = finf();
        int idx = 0;
        bool v = false;
        if (ii < e) {
            const float4 c = g_sorted[boff + ii];
            d = fmaf(qp.x, c.x, fmaf(qp.y, c.y, fmaf(qp.z, c.z, c.w)));
            v = (d <= cmax);
            if (v) idx = g_sortidx[boff + ii];     // lazy: only shuffled-from lanes
        }
        unsigned bal = __ballot_sync(FULLMASK, v);
        if (bal) {
            do {
                const int src = __ffs(bal) - 1; bal &= bal - 1;
                const float dv = __shfl_sync(FULLMASK, d,   src);
                const int   iv = __shfl_sync(FULLMASK, idx, src);
                insert_lex(dv, iv, lane, ld, li);  // stale-threshold extras are no-ops
            } while (bal);
            cmax = __shfl_sync(FULLMASK, ld, 15);
        }
    }
}

// =====================================================================
// G1: bounds reduce + zero histogram + write grid params (single block)
// =====================================================================
__global__ __launch_bounds__(1024) void grid_setup_kernel(const float4* __restrict__ xytp)
{
    __shared__ float red[6][32];
    for (int i = threadIdx.x; i < B_ * NC; i += 1024) g_cellcnt[i] = 0;

    float mn[3] = { finf(), finf(), finf() };
    float mx[3] = { -finf(), -finf(), -finf() };
    for (int i = threadIdx.x; i < B_ * N_; i += 1024) {
        const float4 v = xytp[i];
        mn[0] = fminf(mn[0], v.x); mx[0] = fmaxf(mx[0], v.x);
        mn[1] = fminf(mn[1], v.y); mx[1] = fmaxf(mx[1], v.y);
        mn[2] = fminf(mn[2], v.z); mx[2] = fmaxf(mx[2], v.z);
    }
#pragma unroll
    for (int off = 16; off; off >>= 1) {
#pragma unroll
        for (int d = 0; d < 3; ++d) {
            mn[d] = fminf(mn[d], __shfl_xor_sync(FULLMASK, mn[d], off));
            mx[d] = fmaxf(mx[d], __shfl_xor_sync(FULLMASK, mx[d], off));
        }
    }
    const int warp = threadIdx.x >> 5, lane = threadIdx.x & 31;
    if (lane == 0) {
#pragma unroll
        for (int d = 0; d < 3; ++d) { red[d][warp] = mn[d]; red[3 + d][warp] = mx[d]; }
    }
    __syncthreads();
    if (threadIdx.x < 32) {
        float a[6];
#pragma unroll
        for (int d = 0; d < 6; ++d) a[d] = red[d][lane];
#pragma unroll
        for (int off = 16; off; off >>= 1) {
#pragma unroll
            for (int d = 0; d < 3; ++d) {
                a[d]     = fminf(a[d],     __shfl_xor_sync(FULLMASK, a[d],     off));
                a[3 + d] = fmaxf(a[3 + d], __shfl_xor_sync(FULLMASK, a[3 + d], off));
            }
        }
        if (lane == 0) {
            float h[3], o[3];
#pragma unroll
            for (int d = 0; d < 3; ++d) {
                o[d] = a[d] - 1e-4f;
                h[d] = fmaxf((a[3 + d] - a[d] + 2e-4f) * (1.f / GR), 1e-6f);
            }
            g_grid[0] = o[0]; g_grid[1] = o[1]; g_grid[2] = o[2];
            g_grid[3] = h[0]; g_grid[4] = h[1]; g_grid[5] = h[2];
            g_grid[6] = fminf(h[0], fminf(h[1], h[2]));
            g_grid[7] = 1.f / h[0]; g_grid[8] = 1.f / h[1]; g_grid[9] = 1.f / h[2];
        }
    }
}

// =====================================================================
// G2: per-point cell id + histogram
// =====================================================================
__global__ __launch_bounds__(256) void cell_hist_kernel(const float4* __restrict__ xytp)
{
    const int i = blockIdx.x * 256 + threadIdx.x;
    const int b = i >> 13;
    const float4 v = xytp[i];
    const int cx = min(GR - 1, max(0, (int)((v.x - g_grid[0]) * g_grid[7])));
    const int cy = min(GR - 1, max(0, (int)((v.y - g_grid[1]) * g_grid[8])));
    const int cz = min(GR - 1, max(0, (int)((v.z - g_grid[2]) * g_grid[9])));
    const int cid = (cz * GR + cy) * GR + cx;
    g_cellid[i] = cid;
    atomicAdd(&g_cellcnt[b * NC + cid], 1);
}

// =====================================================================
// G3: exclusive prefix scan of 4096 counts per batch (block per batch)
// =====================================================================
__global__ __launch_bounds__(1024) void prefix_kernel()
{
    __shared__ int wsum[32];
    const int b = blockIdx.x, t = threadIdx.x;
    const int lane = t & 31, warp = t >> 5;
    const int base = b * NC + t * 4;
    const int v0 = g_cellcnt[base + 0];
    const int v1 = g_cellcnt[base + 1];
    const int v2 = g_cellcnt[base + 2];
    const int v3 = g_cellcnt[base + 3];
    const int ts = v0 + v1 + v2 + v3;
    int sc = ts;
#pragma unroll
    for (int off = 1; off < 32; off <<= 1) {
        const int n = __shfl_up_sync(FULLMASK, sc, off);
        if (lane >= off) sc += n;
    }
    if (lane == 31) wsum[warp] = sc;
    __syncthreads();
    if (warp == 0) {
        int ws = wsum[lane];
#pragma unroll
        for (int off = 1; off < 32; off <<= 1) {
            const int n = __shfl_up_sync(FULLMASK, ws, off);
            if (lane >= off) ws += n;
        }
        wsum[lane] = ws;
    }
    __syncthreads();
    const int excl = sc - ts + (warp ? wsum[warp - 1] : 0);
    const int o = b * (NC + 1) + t * 4;
    const int e1 = excl + v0, e2 = e1 + v1, e3 = e2 + v2;
    g_cellstart[o + 0] = excl; g_cellstart[o + 1] = e1;
    g_cellstart[o + 2] = e2;   g_cellstart[o + 3] = e3;
    g_cellptr[base + 0] = excl; g_cellptr[base + 1] = e1;
    g_cellptr[base + 2] = e2;   g_cellptr[base + 3] = e3;
    if (t == 1023) g_cellstart[b * (NC + 1) + NC] = e3 + v3;
}

// =====================================================================
// G4: scatter points into cell-grouped order (pre-transformed)
// =====================================================================
__global__ __launch_bounds__(256) void scatter_kernel(const float4* __restrict__ xytp)
{
    const int i = blockIdx.x * 256 + threadIdx.x;
    const int b = i >> 13;
    const int cid = g_cellid[i];
    const int pos = atomicAdd(&g_cellptr[b * NC + cid], 1);
    const float4 v = xytp[i];
    const float n2 = fmaf(v.z, v.z, fmaf(v.y, v.y, v.x * v.x));
    g_sorted [b * N_ + pos] = make_float4(-2.f * v.x, -2.f * v.y, -2.f * v.z, n2);
    g_sortidx[b * N_ + pos] = i & (N_ - 1);
}

// =====================================================================
// KNN: warp per query (ORIGINAL order, as R6), expanding-shell exact
//      search with deferred-threshold inserts + fused PE-stats partials.
// =====================================================================
__global__ __launch_bounds__(32 * KNN_WPB) void knn_kernel(const float4* __restrict__ xytp,
                                                           const float* __restrict__ pe_w1,
                                                           const float* __restrict__ pe_b1)
{
    __shared__ float sred[KNN_WPB * 8];
    const int tid = threadIdx.x, warp = tid >> 5, lane = tid & 31;
    const int p = blockIdx.x * KNN_WPB + warp;
    const int b = p >> 13;
    const int boff = b * N_;
    const int csb  = b * (NC + 1);

    const float4 qp = xytp[p];
    const float qn2 = fmaf(qp.z, qp.z, fmaf(qp.y, qp.y, qp.x * qp.x));
    const float hmin = g_grid[6];
    const int qcx = min(GR - 1, max(0, (int)((qp.x - g_grid[0]) * g_grid[7])));
    const int qcy = min(GR - 1, max(0, (int)((qp.y - g_grid[1]) * g_grid[8])));
    const int qcz = min(GR - 1, max(0, (int)((qp.z - g_grid[2]) * g_grid[9])));

    float ld = finf(); int li = 0; float cmax = finf();

    for (int r = 0;; ++r) {
        if (r > 0) {
            const float rim = (float)(r - 1) * hmin;
            if (rim * rim >= fmaf(cmax + qn2, 1.0001f, 1e-5f)) break;
            if (r > GR - 1) break;
        }
        for (int dz = -r; dz <= r; ++dz) {
            const int z = qcz + dz;
            if ((unsigned)z > (unsigned)(GR - 1)) continue;
            for (int dy = -r; dy <= r; ++dy) {
                const int y = qcy + dy;
                if ((unsigned)y > (unsigned)(GR - 1)) continue;
                const int row = csb + (z * GR + y) * GR;
                if (dz == -r || dz == r || dy == -r || dy == r) {
                    const int x0 = max(qcx - r, 0), x1 = min(qcx + r, GR - 1);
                    scan_range(g_cellstart[row + x0], g_cellstart[row + x1 + 1],
                               boff, qp, lane, ld, li, cmax);
                } else {
                    const int xl = qcx - r, xr = qcx + r;
                    if (xl >= 0)
                        scan_range(g_cellstart[row + xl], g_cellstart[row + xl + 1],
                                   boff, qp, lane, ld, li, cmax);
                    if (xr <= GR - 1)
                        scan_range(g_cellstart[row + xr], g_cellstart[row + xr + 1],
                                   boff, qp, lane, ld, li, cmax);
                }
            }
        }
    }

    if (lane < 16)
        g_knn[(size_t)p * K_ + lane] = li;         // ascending (d, idx) = top_k order

    // ---- fused PE-stats partials (lanes 0..15 hold the 16 neighbors) ----
    float acc[8];
#pragma unroll
    for (int i = 0; i < 8; ++i) acc[i] = 0.f;
    if (lane < 16) {
        const float4 nb = xytp[boff + li];
        const float r0 = qp.x - nb.x, r1 = qp.y - nb.y, r2 = qp.z - nb.z, r3 = qp.w - nb.w;
#pragma unroll
        for (int f = 0; f < 4; ++f) {
            float h = pe_b1[f];
            h = fmaf(r0, pe_w1[f * 4 + 0], h);
            h = fmaf(r1, pe_w1[f * 4 + 1], h);
            h = fmaf(r2, pe_w1[f * 4 + 2], h);
            h = fmaf(r3, pe_w1[f * 4 + 3], h);
            acc[f]     = h;
            acc[4 + f] = h * h;
        }
    }
#pragma unroll
    for (int i = 0; i < 8; ++i) acc[i] = warp_sum(acc[i]);
    if (lane == 0) {
#pragma unroll
        for (int i = 0; i < 8; ++i) sred[warp * 8 + i] = acc[i];
    }
    __syncthreads();
    if (tid < 8) {
        float s = 0.f;
#pragma unroll
        for (int w = 0; w < KNN_WPB; ++w) s += sred[w * 8 + tid];
        g_part[(size_t)blockIdx.x * 8 + tid] = s;
    }
}

// =====================================================================
// lt: per-point linear transform; split layout (varphi | (psi,alpha))
// =====================================================================
__global__ __launch_bounds__(256) void lt_kernel(const float* __restrict__ features,
                                                 const float* __restrict__ lt_w,
                                                 const float* __restrict__ lt_b)
{
    __shared__ float w[96 * 32];
    __shared__ float bias[96];
    for (int i = threadIdx.x; i < 96 * 32; i += 256) w[i] = lt_w[i];
    if (threadIdx.x < 96) bias[threadIdx.x] = lt_b[threadIdx.x];
    __syncthreads();

    const int p = blockIdx.x * 256 + threadIdx.x;
    float4 f4[8];
    const float4* fr = (const float4*)(features + (size_t)p * C_);
#pragma unroll
    for (int i = 0; i < 8; ++i) f4[i] = fr[i];

#pragma unroll 2
    for (int ch = 0; ch < 32; ++ch) {
        float av = bias[ch], as = bias[32 + ch], aa = bias[64 + ch];
        const float4* wv = (const float4*)(w + ch * 32);
        const float4* ws = (const float4*)(w + (32 + ch) * 32);
        const float4* wa = (const float4*)(w + (64 + ch) * 32);
#pragma unroll
        for (int i = 0; i < 8; ++i) {
            const float4 a = wv[i], s = ws[i], c = wa[i], f = f4[i];
            av = fmaf(f.x, a.x, av); av = fmaf(f.y, a.y, av);
            av = fmaf(f.z, a.z, av); av = fmaf(f.w, a.w, av);
            as = fmaf(f.x, s.x, as); as = fmaf(f.y, s.y, as);
            as = fmaf(f.z, s.z, as); as = fmaf(f.w, s.w, as);
            aa = fmaf(f.x, c.x, aa); aa = fmaf(f.y, c.y, aa);
            aa = fmaf(f.z, c.z, aa); aa = fmaf(f.w, c.w, aa);
        }
        g_ltv [(size_t)p * 32 + ch] = av;
        g_ltpa[(size_t)p * 32 + ch] = make_float2(as, aa);
    }
}

// =====================================================================
// finalize stats (parallel, fixed-order => deterministic)
// =====================================================================
__global__ __launch_bounds__(256) void pe_finalize_kernel()
{
    __shared__ float red[32 * 8];
    __shared__ float tot8[8];
    const int t = threadIdx.x;
    const int ch = t & 7, grp = t >> 3;       // 32 groups of (NPART/32) partials
    float s = 0.f;
    const int base = grp * (NPART / 32);
    for (int i = 0; i < NPART / 32; ++i) s += g_part[(base + i) * 8 + ch];
    red[grp * 8 + ch] = s;
    __syncthreads();
    if (t < 8) {
        float tt = 0.f;
        for (int g = 0; g < 32; ++g) tt += red[g * 8 + t];
        tot8[t] = tt;
    }
    __syncthreads();
    if (t < 4) {
        const float invc = 1.f / (float)(B_ * N_ * K_);
        const float mean = tot8[t] * invc;
        const float var  = fmaf(tot8[4 + t], invc, -mean * mean);
        g_stats[t]     = mean;
        g_stats[4 + t] = rsqrtf(var + 1e-5f);
    }
}

// =====================================================================
// fused main — warp per point, lane = channel
// =====================================================================
__global__ __launch_bounds__(256) void main_kernel(const float4* __restrict__ xytp,
                                                   const float* __restrict__ pe_w1,
                                                   const float* __restrict__ pe_b1,
                                                   const float* __restrict__ pe_gamma,
                                                   const float* __restrict__ pe_beta,
                                                   const float* __restrict__ pe_w2,
                                                   const float* __restrict__ pe_b2,
                                                   const float* __restrict__ ln_gamma,
                                                   const float* __restrict__ ln_beta,
                                                   float* __restrict__ out)
{
    const int warp = threadIdx.x >> 5;
    const int lane = threadIdx.x & 31;
    const int p    = blockIdx.x * 8 + warp;
    const int b    = p >> 13;

    float w1[16], b1v[4], mean[4], rstd[4], gam[4], bet[4], w2a[4];
#pragma unroll
    for (int i = 0; i < 16; ++i) w1[i] = pe_w1[i];
#pragma unroll
    for (int f = 0; f < 4; ++f) {
        b1v[f]  = pe_b1[f];
        mean[f] = g_stats[f];
        rstd[f] = g_stats[4 + f];
        gam[f]  = pe_gamma[f];
        bet[f]  = pe_beta[f];
    }
    {
        const float4 w2 = ((const float4*)pe_w2)[lane];
        w2a[0] = w2.x; w2a[1] = w2.y; w2a[2] = w2.z; w2a[3] = w2.w;
    }
    const float b2 = pe_b2[lane];
    const float lg = ln_gamma[lane];
    const float lb = ln_beta[lane];

    const float  varphi = g_ltv[(size_t)p * 32 + lane];
    const float4 q      = xytp[p];
    const int    myidx  = g_knn[(size_t)p * K_ + (lane & 15)];

    float lgt[16], av[16];
#pragma unroll
    for (int k = 0; k < 16; ++k) {
        const int j = __shfl_sync(FULLMASK, myidx, k);
        const float4 nb = xytp[(size_t)b * N_ + j];
        const float r0 = q.x - nb.x, r1 = q.y - nb.y, r2 = q.z - nb.z, r3 = q.w - nb.w;

        float del = b2;
#pragma unroll
        for (int f = 0; f < 4; ++f) {
            float h = b1v[f];
            h = fmaf(r0, w1[f * 4 + 0], h);
            h = fmaf(r1, w1[f * 4 + 1], h);
            h = fmaf(r2, w1[f * 4 + 2], h);
            h = fmaf(r3, w1[f * 4 + 3], h);
            float u = (h - mean[f]) * rstd[f];
            u = fmaf(u, gam[f], bet[f]);
            u = fmaxf(u, 0.f);
            del = fmaf(u, w2a[f], del);
        }

        const float2 pa = g_ltpa[((size_t)b * N_ + j) * 32 + lane];

        const float pre = (varphi - pa.x) + del;
        const float s1  = warp_sum(pre);
        const float s2  = warp_sum(pre * pre);
        const float mu  = s1 * (1.f / 32.f);
        const float var = fmaf(s2, 1.f / 32.f, -mu * mu);
        const float rs  = rsqrtf(var + 1e-5f);
        lgt[k] = fmaf((pre - mu) * rs, lg, lb);
        av[k]  = pa.y + del;
    }

    float m = -finf();
#pragma unroll
    for (int k = 0; k < 16; ++k) m = fmaxf(m, lgt[k]);
    const float inv_scale = 0.17677669529663687f;   // 1/sqrt(32)
    float se = 0.f, acc = 0.f;
#pragma unroll
    for (int k = 0; k < 16; ++k) {
        const float e = __expf((lgt[k] - m) * inv_scale);
        se  += e;
        acc  = fmaf(e, av[k], acc);
    }
    out[(size_t)p * C_ + lane] = acc / se;
}

// =====================================================================
// Launch  (lt first so the ncu -s 5 -c 1 window lands on knn_kernel)
// =====================================================================
extern "C" void kernel_launch(void* const* d_in, const int* in_sizes, int n_in,
                              void* d_out, int out_size)
{
    const float* xytp     = (const float*)d_in[0];
    const float* features = (const float*)d_in[1];
    const float* pe_w1    = (const float*)d_in[2];
    const float* pe_b1    = (const float*)d_in[3];
    const float* pe_gamma = (const float*)d_in[4];
    const float* pe_beta  = (const float*)d_in[5];
    const float* pe_w2    = (const float*)d_in[6];
    const float* pe_b2    = (const float*)d_in[7];
    const float* lt_w     = (const float*)d_in[8];
    const float* lt_b     = (const float*)d_in[9];
    const float* ln_gamma = (const float*)d_in[10];
    const float* ln_beta  = (const float*)d_in[11];
    float* out = (float*)d_out;
    const float4* xp4 = (const float4*)xytp;

    lt_kernel<<<(B_ * N_) / 256, 256>>>(features, lt_w, lt_b);
    grid_setup_kernel<<<1, 1024>>>(xp4);
    cell_hist_kernel<<<(B_ * N_) / 256, 256>>>(xp4);
    prefix_kernel<<<B_, 1024>>>();
    scatter_kernel<<<(B_ * N_) / 256, 256>>>(xp4);
    knn_kernel<<<KNN_BLOCKS, 32 * KNN_WPB>>>(xp4, pe_w1, pe_b1);
    pe_finalize_kernel<<<1, 256>>>();
    main_kernel<<<(B_ * N_) / 8, 256>>>(xp4, pe_w1, pe_b1,
                                        pe_gamma, pe_beta, pe_w2, pe_b2,
                                        ln_gamma, ln_beta, out);
}